// round 3
// baseline (speedup 1.0000x reference)
#include <cuda_runtime.h>
#include <cstdint>
#include <cstddef>

#define TSTEPS 1024
#define BSZ 128
#define DSZ 256
#define HSZ 512
#define CSZ 1000

// Scratch: x-projections for all timesteps, layout [t][gate][j][b] (b contiguous).
__device__ float g_P[(size_t)TSTEPS * 4 * HSZ * BSZ];
// Double-buffered hidden state, layout [j][b].
__device__ float g_h[2][HSZ * BSZ];
// Grid-wide barrier state (returns to initial state after every full run).
__device__ unsigned g_bar_count;
__device__ unsigned g_bar_gen;

__device__ __forceinline__ float fast_sigmoid(float x) {
    return __fdividef(1.0f, 1.0f + __expf(-x));
}
__device__ __forceinline__ float fast_tanh(float x) {
    return __fdividef(2.0f, 1.0f + __expf(-2.0f * x)) - 1.0f;
}

__device__ __forceinline__ void grid_barrier(unsigned nb) {
    __syncthreads();
    if (threadIdx.x == 0) {
        __threadfence();
        unsigned gen = *(volatile unsigned*)&g_bar_gen;
        unsigned arrived = atomicAdd(&g_bar_count, 1u);
        if (arrived == nb - 1u) {
            atomicExch(&g_bar_count, 0u);
            __threadfence();
            atomicAdd(&g_bar_gen, 1u);
        } else {
            while (*(volatile unsigned*)&g_bar_gen == gen) {
                __nanosleep(32);
            }
        }
        __threadfence();
    }
    __syncthreads();
}

__device__ __forceinline__ void cp16(void* dst_smem, const void* src) {
    unsigned d = (unsigned)__cvta_generic_to_shared(dst_smem);
    asm volatile("cp.async.cg.shared.global [%0], [%1], 16;\n" :: "r"(d), "l"(src));
}

// ---------------------------------------------------------------------------
// Phase 1: P[t][g][j][b] = sum_d x[b][t][d] * Wx[g][d][j]
// grid: (8 j-tiles of 64, 4 gates, 1024 t), block 256.
// ---------------------------------------------------------------------------
__global__ __launch_bounds__(256) void k_xproj(
    const float* __restrict__ x,
    const float* __restrict__ W0, const float* __restrict__ W1,
    const float* __restrict__ W2, const float* __restrict__ W3)
{
    extern __shared__ float sm[];
    float* sW = sm;            // [64][64]
    float* sX = sm + 4096;     // [128][65] (pad 65 to spread banks)

    const int jt = blockIdx.x, g = blockIdx.y, t = blockIdx.z;
    const float* W = (g == 0) ? W0 : (g == 1) ? W1 : (g == 2) ? W2 : W3;
    const int tid = threadIdx.x;
    const int lane = tid & 31, warp = tid >> 5;
    const int j0 = warp * 8;   // 8 warps * 8 = 64 j
    const int b0 = lane * 4;   // 32 lanes * 4 = 128 b

    float acc[8][4];
#pragma unroll
    for (int a = 0; a < 8; ++a)
#pragma unroll
        for (int bb = 0; bb < 4; ++bb) acc[a][bb] = 0.0f;

    for (int kc = 0; kc < DSZ; kc += 64) {
        __syncthreads();
        for (int i = tid; i < 1024; i += 256) {
            int r = i >> 4, c4 = (i & 15) * 4;
            *(float4*)&sW[r * 64 + c4] =
                *(const float4*)&W[(size_t)(kc + r) * HSZ + jt * 64 + c4];
        }
        for (int i = tid; i < 2048; i += 256) {
            int b = i >> 4, d4 = (i & 15) * 4;
            float4 v = *(const float4*)&x[((size_t)b * TSTEPS + t) * DSZ + kc + d4];
            sX[b * 65 + d4 + 0] = v.x;
            sX[b * 65 + d4 + 1] = v.y;
            sX[b * 65 + d4 + 2] = v.z;
            sX[b * 65 + d4 + 3] = v.w;
        }
        __syncthreads();
#pragma unroll 4
        for (int k = 0; k < 64; ++k) {
            float4 w0 = *(const float4*)&sW[k * 64 + j0];
            float4 w1 = *(const float4*)&sW[k * 64 + j0 + 4];
            float xb0 = sX[(b0 + 0) * 65 + k];
            float xb1 = sX[(b0 + 1) * 65 + k];
            float xb2 = sX[(b0 + 2) * 65 + k];
            float xb3 = sX[(b0 + 3) * 65 + k];
            float wv[8] = {w0.x, w0.y, w0.z, w0.w, w1.x, w1.y, w1.z, w1.w};
#pragma unroll
            for (int jj = 0; jj < 8; ++jj) {
                acc[jj][0] += wv[jj] * xb0;
                acc[jj][1] += wv[jj] * xb1;
                acc[jj][2] += wv[jj] * xb2;
                acc[jj][3] += wv[jj] * xb3;
            }
        }
    }
    size_t obase = (((size_t)t * 4 + g) * HSZ + jt * 64 + j0) * BSZ + b0;
#pragma unroll
    for (int jj = 0; jj < 8; ++jj) {
        float4 o = make_float4(acc[jj][0], acc[jj][1], acc[jj][2], acc[jj][3]);
        *(float4*)&g_P[obase + (size_t)jj * BSZ] = o;
    }
}

// ---------------------------------------------------------------------------
// Phase 2: persistent recurrent scan. 128 CTAs, 256 threads.
// CTA ct owns h columns [ct*4, ct*4+4) for ALL 4 gates.
// Thread (g = tid>>6, bq = tid&63) computes pre-act for 2 batches x 4 cols of gate g.
// SMEM floats: sh_h[2][128][128]=32768 | sh_W[4][512][4]=8192 | sh_pre[16][128]=2048 | sh_c[4][128]=512
// ---------------------------------------------------------------------------
__global__ __launch_bounds__(256, 1) void k_rnn(
    const float* __restrict__ Wgh, const float* __restrict__ Wih,
    const float* __restrict__ Wfh, const float* __restrict__ Woh,
    const float* __restrict__ bgp, const float* __restrict__ bip,
    const float* __restrict__ bfp, const float* __restrict__ bop)
{
    extern __shared__ float sm[];
    float* sh_h = sm;                  // 32768
    float* sh_W = sm + 32768;          // 8192
    float* sh_pre = sm + 40960;        // 2048
    float* sh_c = sm + 43008;          // 512

    const int ct = blockIdx.x;
    const int j0 = ct * 4;
    const int tid = threadIdx.x;
    const int g = tid >> 6;        // gate, uniform per warp
    const int bq = tid & 63;
    const int b0 = bq * 2;

    const float* Wh = (g == 0) ? Wgh : (g == 1) ? Wih : (g == 2) ? Wfh : Woh;
    const float* bv = (g == 0) ? bgp : (g == 1) ? bip : (g == 2) ? bfp : bop;

    // Resident recurrent weights: sh_W[g][k][0..3] = Wh[k][j0..j0+3]
    for (int k = bq; k < HSZ; k += 64) {
        *(float4*)&sh_W[(g * HSZ + k) * 4] = *(const float4*)&Wh[(size_t)k * HSZ + j0];
    }
    float bias[4];
#pragma unroll
    for (int jj = 0; jj < 4; ++jj) bias[jj] = bv[j0 + jj];

    for (int i = tid; i < 512; i += 256) sh_c[i] = 0.0f;
    for (int i = tid; i < 512; i += 256) {
        int jj = i >> 7, b = i & 127;
        g_h[0][(j0 + jj) * BSZ + b] = 0.0f;
    }
    grid_barrier(gridDim.x);

    const int col = (tid & 31) * 4;
    const int rb = tid >> 5;

    for (int t = 0; t < TSTEPS; ++t) {
        const float* hb = g_h[t & 1];
        float* hn = g_h[(t + 1) & 1];

        // init accumulators with x-projection + bias
        float acc[2][4];
        {
            const float* Pg = &g_P[(((size_t)t * 4 + g) * HSZ + j0) * BSZ + b0];
#pragma unroll
            for (int jj = 0; jj < 4; ++jj) {
                float2 p = *(const float2*)&Pg[jj * BSZ];
                acc[0][jj] = p.x + bias[jj];
                acc[1][jj] = p.y + bias[jj];
            }
        }

        // prefetch k-chunk 0 into buffer 0
#pragma unroll
        for (int r = 0; r < 16; ++r) {
            int row = rb + r * 8;
            cp16(&sh_h[row * 128 + col], &hb[row * 128 + col]);
        }
        asm volatile("cp.async.commit_group;");

        for (int cc = 0; cc < 4; ++cc) {
            if (cc < 3) {
                int kc = (cc + 1) * 128;
                float* dstb = &sh_h[((cc + 1) & 1) * 16384];
#pragma unroll
                for (int r = 0; r < 16; ++r) {
                    int row = rb + r * 8;
                    cp16(&dstb[row * 128 + col], &hb[(kc + row) * 128 + col]);
                }
                asm volatile("cp.async.commit_group;");
                asm volatile("cp.async.wait_group 1;");
            } else {
                asm volatile("cp.async.wait_group 0;");
            }
            __syncthreads();
            const float* hs = &sh_h[(cc & 1) * 16384];
            const float4* wq = (const float4*)&sh_W[(g * HSZ + cc * 128) * 4];
#pragma unroll 4
            for (int k = 0; k < 128; ++k) {
                float4 w = wq[k];                                   // broadcast LDS
                float2 h2 = *(const float2*)&hs[k * 128 + b0];      // conflict-free
                acc[0][0] += h2.x * w.x;
                acc[0][1] += h2.x * w.y;
                acc[0][2] += h2.x * w.z;
                acc[0][3] += h2.x * w.w;
                acc[1][0] += h2.y * w.x;
                acc[1][1] += h2.y * w.y;
                acc[1][2] += h2.y * w.z;
                acc[1][3] += h2.y * w.w;
            }
            __syncthreads();
        }

        // publish pre-activations for gate exchange
#pragma unroll
        for (int jj = 0; jj < 4; ++jj) {
            *(float2*)&sh_pre[(g * 4 + jj) * 128 + b0] =
                make_float2(acc[0][jj], acc[1][jj]);
        }
        __syncthreads();

        // combine gates, update c, write h_new
#pragma unroll
        for (int r = 0; r < 2; ++r) {
            int idx = tid + r * 256;        // 0..511 = 4 jj x 128 b
            int jj = idx >> 7, b = idx & 127;
            float pg = sh_pre[(0  + jj) * 128 + b];
            float pi = sh_pre[(4  + jj) * 128 + b];
            float pf = sh_pre[(8  + jj) * 128 + b];
            float po = sh_pre[(12 + jj) * 128 + b];
            float gv = fast_tanh(pg);
            float iv = fast_sigmoid(pi);
            float fv = fast_sigmoid(pf);
            float ov = fast_sigmoid(po);
            float cv = gv * iv + sh_c[jj * 128 + b] * fv;
            sh_c[jj * 128 + b] = cv;
            hn[(j0 + jj) * BSZ + b] = fast_tanh(cv) * ov;
        }
        grid_barrier(gridDim.x);
    }
}

// ---------------------------------------------------------------------------
// Phase 3: out[b][c] = h_final[b] . Wph[:,c] + bp[c].  grid(1000), block(128).
// h_final lives in g_h[0] (1024 steps -> last write lands in buffer 0).
// ---------------------------------------------------------------------------
__global__ __launch_bounds__(128) void k_out(
    const float* __restrict__ Wp, const float* __restrict__ bp,
    float* __restrict__ out)
{
    int c = blockIdx.x;
    int b = threadIdx.x;
    const float* h = g_h[0];
    float acc = 0.0f;
#pragma unroll 8
    for (int k = 0; k < HSZ; ++k)
        acc += h[k * BSZ + b] * Wp[(size_t)k * CSZ + c];
    out[b * CSZ + c] = acc + bp[c];
}

// ---------------------------------------------------------------------------

extern "C" void kernel_launch(void* const* d_in, const int* in_sizes, int n_in,
                              void* d_out, int out_size) {
    const float* x   = (const float*)d_in[0];
    const float* Wgx = (const float*)d_in[1];
    const float* Wgh = (const float*)d_in[2];
    const float* bg  = (const float*)d_in[3];
    const float* Wix = (const float*)d_in[4];
    const float* Wih = (const float*)d_in[5];
    const float* bi  = (const float*)d_in[6];
    const float* Wfx = (const float*)d_in[7];
    const float* Wfh = (const float*)d_in[8];
    const float* bf  = (const float*)d_in[9];
    const float* Wox = (const float*)d_in[10];
    const float* Woh = (const float*)d_in[11];
    const float* bo  = (const float*)d_in[12];
    const float* Wph = (const float*)d_in[13];
    const float* bp  = (const float*)d_in[14];
    float* out = (float*)d_out;

    (void)in_sizes; (void)n_in; (void)out_size;

    static_assert(sizeof(float) == 4, "");

    cudaFuncSetAttribute(k_xproj, cudaFuncAttributeMaxDynamicSharedMemorySize,
                         (4096 + 128 * 65) * 4);
    cudaFuncSetAttribute(k_rnn, cudaFuncAttributeMaxDynamicSharedMemorySize,
                         43520 * 4);

    dim3 g1(8, 4, TSTEPS);
    k_xproj<<<g1, 256, (4096 + 128 * 65) * 4>>>(x, Wgx, Wix, Wfx, Wox);
    k_rnn<<<128, 256, 43520 * 4>>>(Wgh, Wih, Wfh, Woh, bg, bi, bf, bo);
    k_out<<<CSZ, 128>>>(Wph, bp, out);
}